// round 1
// baseline (speedup 1.0000x reference)
#include <cuda_runtime.h>
#include <math.h>

#define NB    8
#define LSEQ  2048
#define MTOK  (NB*LSEQ)     // 16384 tokens
#define DIN   64
#define DOUT  64
#define DM    512
#define DS    256
#define NL    4

// ---------------- scratch (device globals; no allocation allowed) ----------------
__device__ float g_x   [MTOK*DM];          // 32 MB activations
__device__ float g_bu  [MTOK*DM];          // Bu packed [re(256) | im(256)]
__device__ float g_h   [MTOK*DM];          // h  packed [re | im]
__device__ float g_z   [MTOK*DM];          // LRU output
__device__ float g_g   [MTOK*2*DM];        // GLU pre-activations [g1(512) | g2(512)]
__device__ float g_Wb  [NL*DM*DM];         // gamma-scaled [Bre ; Bim] rows
__device__ float g_Wc  [NL*DM*DM];         // [Cre | -Cim] along K
__device__ float g_Wglu[NL*2*DM*DM];       // [W1 ; W2] rows
__device__ float g_lre [NL*DS];
__device__ float g_lim [NL*DS];
__device__ float g_gam [NL*DS];
__device__ float g_sres[NL];

// ---------------- prep kernels ----------------
__global__ void prep_lam_kernel(const float* __restrict__ nu_log,
                                const float* __restrict__ th_log,
                                const float* __restrict__ rlog) {
    int i = blockIdx.x * blockDim.x + threadIdx.x;
    if (i < NL*DS) {
        float nu = expf(nu_log[i]);
        float r  = expf(-nu);
        float th = expf(th_log[i]);
        g_lre[i] = r * cosf(th);
        g_lim[i] = r * sinf(th);
        g_gam[i] = sqrtf(fmaxf(1.0f - r*r, 0.0f));
    }
    if (i < NL) g_sres[i] = 1.0f / (1.0f + expf(-rlog[i]));
}

__global__ void prep_wb_kernel(const float* __restrict__ Bre,
                               const float* __restrict__ Bim) {
    int idx = blockIdx.x * blockDim.x + threadIdx.x;
    if (idx >= NL*DM*DM) return;
    int l   = idx / (DM*DM);
    int rem = idx - l*(DM*DM);
    int n   = rem / DM;      // output row 0..511
    int k   = rem - n*DM;
    float v;
    if (n < DS) v = g_gam[l*DS + n]      * Bre[((size_t)l*DS + n)*DM + k];
    else        v = g_gam[l*DS + n - DS] * Bim[((size_t)l*DS + (n-DS))*DM + k];
    g_Wb[idx] = v;
}

__global__ void prep_wc_kernel(const float* __restrict__ Cre,
                               const float* __restrict__ Cim) {
    int idx = blockIdx.x * blockDim.x + threadIdx.x;
    if (idx >= NL*DM*DM) return;
    int l   = idx / (DM*DM);
    int rem = idx - l*(DM*DM);
    int d   = rem / DM;
    int k   = rem - d*DM;
    float v;
    if (k < DS) v =  Cre[((size_t)l*DM + d)*DS + k];
    else        v = -Cim[((size_t)l*DM + d)*DS + (k-DS)];
    g_Wc[idx] = v;
}

__global__ void prep_wglu_kernel(const float* __restrict__ W1,
                                 const float* __restrict__ W2) {
    int idx = blockIdx.x * blockDim.x + threadIdx.x;
    if (idx >= NL*2*DM*DM) return;
    int l   = idx / (2*DM*DM);
    int rem = idx - l*(2*DM*DM);
    int o   = rem / DM;      // 0..1023
    int k   = rem - o*DM;
    float v;
    if (o < DM) v = W1[((size_t)l*DM + o)*DM + k];
    else        v = W2[((size_t)l*DM + (o-DM))*DM + k];
    g_Wglu[idx] = v;
}

// ---------------- SGEMM: C[m,n] = sum_k A[m,k]*W[n,k]  (+ optional Dv[n]*Xr[m,n]) ----
#define BMT 128
#define BNT 128
#define BKT 16

__global__ __launch_bounds__(256)
void sgemm_kernel(const float* __restrict__ A, const float* __restrict__ W,
                  float* __restrict__ C, int M, int N, int K,
                  const float* __restrict__ Dvec, const float* __restrict__ Xres) {
    __shared__ float As[BKT][BMT];
    __shared__ float Ws[BKT][BNT];
    const int bm  = blockIdx.y * BMT;
    const int bn  = blockIdx.x * BNT;
    const int tid = threadIdx.x;
    const int tx  = tid & 15;          // n-group
    const int ty  = tid >> 4;          // m-group
    const int lr  = tid >> 2;          // 0..63 load row
    const int lc  = (tid & 3) << 2;    // 0,4,8,12 load col

    float acc[8][8];
#pragma unroll
    for (int i = 0; i < 8; i++)
#pragma unroll
        for (int j = 0; j < 8; j++) acc[i][j] = 0.0f;

    for (int k0 = 0; k0 < K; k0 += BKT) {
#pragma unroll
        for (int h = 0; h < 2; h++) {
            int r = lr + h*64;
            float4 va = *reinterpret_cast<const float4*>(&A[(size_t)(bm + r)*K + k0 + lc]);
            As[lc+0][r] = va.x; As[lc+1][r] = va.y; As[lc+2][r] = va.z; As[lc+3][r] = va.w;
            float4 vw = make_float4(0.f, 0.f, 0.f, 0.f);
            if (bn + r < N)
                vw = *reinterpret_cast<const float4*>(&W[(size_t)(bn + r)*K + k0 + lc]);
            Ws[lc+0][r] = vw.x; Ws[lc+1][r] = vw.y; Ws[lc+2][r] = vw.z; Ws[lc+3][r] = vw.w;
        }
        __syncthreads();
#pragma unroll
        for (int kk = 0; kk < BKT; kk++) {
            float a[8], w[8];
            *(float4*)&a[0] = *(const float4*)&As[kk][ty*8];
            *(float4*)&a[4] = *(const float4*)&As[kk][ty*8 + 4];
            *(float4*)&w[0] = *(const float4*)&Ws[kk][tx*8];
            *(float4*)&w[4] = *(const float4*)&Ws[kk][tx*8 + 4];
#pragma unroll
            for (int i = 0; i < 8; i++)
#pragma unroll
                for (int j = 0; j < 8; j++)
                    acc[i][j] = fmaf(a[i], w[j], acc[i][j]);
        }
        __syncthreads();
    }

    const int col0 = bn + tx*8;
    if (col0 < N) {   // N is always a multiple of 8 here
#pragma unroll
        for (int i = 0; i < 8; i++) {
            size_t row = (size_t)(bm + ty*8 + i);
            float4 v0 = make_float4(acc[i][0], acc[i][1], acc[i][2], acc[i][3]);
            float4 v1 = make_float4(acc[i][4], acc[i][5], acc[i][6], acc[i][7]);
            if (Dvec) {
                float4 x0 = *(const float4*)&Xres[row*N + col0];
                float4 x1 = *(const float4*)&Xres[row*N + col0 + 4];
                float4 d0 = *(const float4*)&Dvec[col0];
                float4 d1 = *(const float4*)&Dvec[col0 + 4];
                v0.x = fmaf(d0.x, x0.x, v0.x); v0.y = fmaf(d0.y, x0.y, v0.y);
                v0.z = fmaf(d0.z, x0.z, v0.z); v0.w = fmaf(d0.w, x0.w, v0.w);
                v1.x = fmaf(d1.x, x1.x, v1.x); v1.y = fmaf(d1.y, x1.y, v1.y);
                v1.z = fmaf(d1.z, x1.z, v1.z); v1.w = fmaf(d1.w, x1.w, v1.w);
            }
            *(float4*)&C[row*N + col0]     = v0;
            *(float4*)&C[row*N + col0 + 4] = v1;
        }
    }
}

// ---------------- LRU scan: h_t = lam*h_{t-1} + Bu_t, per (batch, state) --------
__global__ void scan_kernel(const float* __restrict__ Bu, float* __restrict__ H,
                            const float* __restrict__ lre_g,
                            const float* __restrict__ lim_g) {
    int n = threadIdx.x;     // 0..255 state index
    int b = blockIdx.x;      // 0..7 batch
    float lre = lre_g[n];
    float lim = lim_g[n];
    size_t base = (size_t)b * LSEQ * DM + n;
    float hre = 0.0f, him = 0.0f;
#pragma unroll 4
    for (int t = 0; t < LSEQ; ++t) {
        size_t off = base + (size_t)t * DM;
        float bre = Bu[off];
        float bim = Bu[off + DS];
        float nre = fmaf(lre, hre, fmaf(-lim, him, bre));
        float nim = fmaf(lim, hre, fmaf( lre, him, bim));
        hre = nre; him = nim;
        H[off]      = hre;
        H[off + DS] = him;
    }
}

// ---------------- GLU + gated residual: x += s * g1 * sigmoid(g2) --------------
__global__ void glu_kernel(const float* __restrict__ g, float* __restrict__ x,
                           const float* __restrict__ sres, int l) {
    int idx = blockIdx.x * blockDim.x + threadIdx.x;   // over MTOK*DM/4
    const int total = MTOK * DM / 4;
    if (idx >= total) return;
    float s = sres[l];
    int m  = idx / (DM/4);
    int d4 = idx - m*(DM/4);
    size_t gbase = (size_t)m * (2*DM) + d4*4;
    float4 a  = *(const float4*)(g + gbase);
    float4 bg = *(const float4*)(g + gbase + DM);
    float4 xv = *(const float4*)(x + (size_t)idx*4);
    xv.x = fmaf(s * a.x, 1.0f/(1.0f + expf(-bg.x)), xv.x);
    xv.y = fmaf(s * a.y, 1.0f/(1.0f + expf(-bg.y)), xv.y);
    xv.z = fmaf(s * a.z, 1.0f/(1.0f + expf(-bg.z)), xv.z);
    xv.w = fmaf(s * a.w, 1.0f/(1.0f + expf(-bg.w)), xv.w);
    *(float4*)(x + (size_t)idx*4) = xv;
}

// ---------------- host launch ----------------
extern "C" void kernel_launch(void* const* d_in, const int* in_sizes, int n_in,
                              void* d_out, int out_size) {
    const float* u      = (const float*)d_in[0];
    const float* enc_w  = (const float*)d_in[1];
    const float* dec_w  = (const float*)d_in[2];
    const float* nu_log = (const float*)d_in[3];
    const float* th_log = (const float*)d_in[4];
    const float* Bre    = (const float*)d_in[5];
    const float* Bim    = (const float*)d_in[6];
    const float* Cre    = (const float*)d_in[7];
    const float* Cim    = (const float*)d_in[8];
    const float* Dv     = (const float*)d_in[9];
    const float* W1     = (const float*)d_in[10];
    const float* W2     = (const float*)d_in[11];
    const float* rlog   = (const float*)d_in[12];
    float* out = (float*)d_out;

    float *px, *pbu, *ph, *pz, *pg, *pWb, *pWc, *pWglu, *plre, *plim, *psres;
    cudaGetSymbolAddress((void**)&px,    g_x);
    cudaGetSymbolAddress((void**)&pbu,   g_bu);
    cudaGetSymbolAddress((void**)&ph,    g_h);
    cudaGetSymbolAddress((void**)&pz,    g_z);
    cudaGetSymbolAddress((void**)&pg,    g_g);
    cudaGetSymbolAddress((void**)&pWb,   g_Wb);
    cudaGetSymbolAddress((void**)&pWc,   g_Wc);
    cudaGetSymbolAddress((void**)&pWglu, g_Wglu);
    cudaGetSymbolAddress((void**)&plre,  g_lre);
    cudaGetSymbolAddress((void**)&plim,  g_lim);
    cudaGetSymbolAddress((void**)&psres, g_sres);

    // weight prep (cheap, deterministic each call)
    prep_lam_kernel <<<(NL*DS + 255)/256, 256>>>(nu_log, th_log, rlog);
    prep_wb_kernel  <<<(NL*DM*DM + 255)/256, 256>>>(Bre, Bim);
    prep_wc_kernel  <<<(NL*DM*DM + 255)/256, 256>>>(Cre, Cim);
    prep_wglu_kernel<<<(NL*2*DM*DM + 255)/256, 256>>>(W1, W2);

    // encoder: x = u @ enc_w^T   [16384,64] x [512,64]^T
    sgemm_kernel<<<dim3((DM + BNT-1)/BNT, MTOK/BMT), 256>>>(
        u, enc_w, px, MTOK, DM, DIN, nullptr, nullptr);

    for (int l = 0; l < NL; ++l) {
        // Bu (packed re|im, gamma folded): [16384,512] x [512,512]^T
        sgemm_kernel<<<dim3(DM/BNT, MTOK/BMT), 256>>>(
            px, pWb + (size_t)l*DM*DM, pbu, MTOK, DM, DM, nullptr, nullptr);
        // sequential complex scan along L
        scan_kernel<<<NB, DS>>>(pbu, ph, plre + l*DS, plim + l*DS);
        // z = Re(C h) + D*x : h_packed @ [Cre|-Cim]^T with fused D*x epilogue
        sgemm_kernel<<<dim3(DM/BNT, MTOK/BMT), 256>>>(
            ph, pWc + (size_t)l*DM*DM, pz, MTOK, DM, DM, Dv + l*DM, px);
        // GLU pre-activations: g = z @ [W1;W2]^T  (N = 1024)
        sgemm_kernel<<<dim3(2*DM/BNT, MTOK/BMT), 256>>>(
            pz, pWglu + (size_t)l*2*DM*DM, pg, MTOK, 2*DM, DM, nullptr, nullptr);
        // x += s * g1 * sigmoid(g2)
        glu_kernel<<<(MTOK*DM/4 + 255)/256, 256>>>(pg, px, psres, l);
    }

    // decoder: out = x @ dec_w^T  [16384,512] x [64,512]^T
    sgemm_kernel<<<dim3((DOUT + BNT-1)/BNT, MTOK/BMT), 256>>>(
        px, dec_w, out, MTOK, DOUT, DM, nullptr, nullptr);
}

// round 2
// speedup vs baseline: 1.1506x; 1.1506x over previous
#include <cuda_runtime.h>
#include <math.h>

#define NB    8
#define LSEQ  2048
#define MTOK  (NB*LSEQ)     // 16384 tokens
#define DIN   64
#define DOUT  64
#define DM    512
#define DS    256
#define NL    4
#define NCH   16
#define CHLEN (LSEQ/NCH)    // 128

// ---------------- scratch (device globals; no allocation allowed) ----------------
__device__ float g_x   [MTOK*DM];
__device__ float g_bu  [MTOK*DM];          // Bu packed [re(256) | im(256)]
__device__ float g_h   [MTOK*DM];          // h  packed [re | im]
__device__ float g_z   [MTOK*DM];          // LRU output
__device__ float g_Wb  [NL*DM*DM];         // gamma-scaled [Bre ; Bim] rows
__device__ float g_Wc  [NL*DM*DM];         // [Cre | -Cim] along K
__device__ float g_Wglu[NL*2*DM*DM];       // interleaved rows: 2o=W1[o], 2o+1=W2[o]
__device__ float g_lre [NL*DS];
__device__ float g_lim [NL*DS];
__device__ float g_gam [NL*DS];
__device__ float g_sres[NL];
__device__ float g_cend[NB*NCH*2*DS];      // chunk-local end states
__device__ float g_cin [NB*NCH*2*DS];      // chunk carry-in states

// ---------------- prep kernels ----------------
__global__ void prep_lam_kernel(const float* __restrict__ nu_log,
                                const float* __restrict__ th_log,
                                const float* __restrict__ rlog) {
    int i = blockIdx.x * blockDim.x + threadIdx.x;
    if (i < NL*DS) {
        float nu = expf(nu_log[i]);
        float r  = expf(-nu);
        float th = expf(th_log[i]);
        g_lre[i] = r * cosf(th);
        g_lim[i] = r * sinf(th);
        g_gam[i] = sqrtf(fmaxf(1.0f - r*r, 0.0f));
    }
    if (i < NL) g_sres[i] = 1.0f / (1.0f + expf(-rlog[i]));
}

__global__ void prep_wb_kernel(const float* __restrict__ Bre,
                               const float* __restrict__ Bim) {
    int idx = blockIdx.x * blockDim.x + threadIdx.x;
    if (idx >= NL*DM*DM) return;
    int l   = idx / (DM*DM);
    int rem = idx - l*(DM*DM);
    int n   = rem / DM;
    int k   = rem - n*DM;
    float v;
    if (n < DS) v = g_gam[l*DS + n]      * Bre[((size_t)l*DS + n)*DM + k];
    else        v = g_gam[l*DS + n - DS] * Bim[((size_t)l*DS + (n-DS))*DM + k];
    g_Wb[idx] = v;
}

__global__ void prep_wc_kernel(const float* __restrict__ Cre,
                               const float* __restrict__ Cim) {
    int idx = blockIdx.x * blockDim.x + threadIdx.x;
    if (idx >= NL*DM*DM) return;
    int l   = idx / (DM*DM);
    int rem = idx - l*(DM*DM);
    int d   = rem / DM;
    int k   = rem - d*DM;
    float v;
    if (k < DS) v =  Cre[((size_t)l*DM + d)*DS + k];
    else        v = -Cim[((size_t)l*DM + d)*DS + (k-DS)];
    g_Wc[idx] = v;
}

// interleave W1/W2 rows so a 128-wide output tile holds (g1,g2) pairs
__global__ void prep_wglu_kernel(const float* __restrict__ W1,
                                 const float* __restrict__ W2) {
    int idx = blockIdx.x * blockDim.x + threadIdx.x;
    if (idx >= NL*2*DM*DM) return;
    int l   = idx / (2*DM*DM);
    int rem = idx - l*(2*DM*DM);
    int n   = rem / DM;      // packed row 0..1023
    int k   = rem - n*DM;
    int o   = n >> 1;
    float v = (n & 1) ? W2[((size_t)l*DM + o)*DM + k]
                      : W1[((size_t)l*DM + o)*DM + k];
    g_Wglu[idx] = v;
}

// ---------------- pipelined SGEMM ----------------
// C[m,n] = sum_k A[m,k]*W[n,k]; epi: 0 plain, 1 +=D[n]*X[m,n] store to C,
// 2 GLU: Xout[m,o] += s * c_even * sigmoid(c_odd), o = n/2
#define BMT 128
#define BNT 128
#define BKT 16

__global__ __launch_bounds__(256, 2)
void sgemm_kernel(const float* __restrict__ A, const float* __restrict__ W,
                  float* __restrict__ C, int M, int N, int K, int epi,
                  const float* __restrict__ Dvec, const float* __restrict__ Xres,
                  const float* __restrict__ sres_p, float* __restrict__ Xout) {
    __shared__ float As[2][BKT][BMT];
    __shared__ float Ws[2][BKT][BNT];
    const int bm  = blockIdx.y * BMT;
    const int bn  = blockIdx.x * BNT;
    const int tid = threadIdx.x;
    const int tx  = tid & 15;
    const int ty  = tid >> 4;
    const int lr  = tid >> 2;          // 0..63
    const int lc  = (tid & 3) << 2;    // 0,4,8,12

    float acc[8][8];
#pragma unroll
    for (int i = 0; i < 8; i++)
#pragma unroll
        for (int j = 0; j < 8; j++) acc[i][j] = 0.0f;

    const int nk = K / BKT;

    // prologue: tile 0 -> buf 0
    float4 na0, na1, nw0, nw1;
    {
        int r0 = lr, r1 = lr + 64;
        na0 = *reinterpret_cast<const float4*>(&A[(size_t)(bm + r0)*K + lc]);
        na1 = *reinterpret_cast<const float4*>(&A[(size_t)(bm + r1)*K + lc]);
        nw0 = make_float4(0.f,0.f,0.f,0.f); nw1 = nw0;
        if (bn + r0 < N) nw0 = *reinterpret_cast<const float4*>(&W[(size_t)(bn + r0)*K + lc]);
        if (bn + r1 < N) nw1 = *reinterpret_cast<const float4*>(&W[(size_t)(bn + r1)*K + lc]);
        As[0][lc+0][lr] = na0.x; As[0][lc+1][lr] = na0.y; As[0][lc+2][lr] = na0.z; As[0][lc+3][lr] = na0.w;
        As[0][lc+0][lr+64] = na1.x; As[0][lc+1][lr+64] = na1.y; As[0][lc+2][lr+64] = na1.z; As[0][lc+3][lr+64] = na1.w;
        Ws[0][lc+0][lr] = nw0.x; Ws[0][lc+1][lr] = nw0.y; Ws[0][lc+2][lr] = nw0.z; Ws[0][lc+3][lr] = nw0.w;
        Ws[0][lc+0][lr+64] = nw1.x; Ws[0][lc+1][lr+64] = nw1.y; Ws[0][lc+2][lr+64] = nw1.z; Ws[0][lc+3][lr+64] = nw1.w;
    }
    __syncthreads();

    int buf = 0;
    for (int t = 0; t < nk; ++t) {
        const bool pf = (t + 1 < nk);
        if (pf) {
            int k0 = (t + 1) * BKT;
            na0 = *reinterpret_cast<const float4*>(&A[(size_t)(bm + lr)*K + k0 + lc]);
            na1 = *reinterpret_cast<const float4*>(&A[(size_t)(bm + lr + 64)*K + k0 + lc]);
            nw0 = make_float4(0.f,0.f,0.f,0.f); nw1 = nw0;
            if (bn + lr < N)      nw0 = *reinterpret_cast<const float4*>(&W[(size_t)(bn + lr)*K + k0 + lc]);
            if (bn + lr + 64 < N) nw1 = *reinterpret_cast<const float4*>(&W[(size_t)(bn + lr + 64)*K + k0 + lc]);
        }
#pragma unroll
        for (int kk = 0; kk < BKT; kk++) {
            float a[8], w[8];
            *(float4*)&a[0] = *(const float4*)&As[buf][kk][ty*8];
            *(float4*)&a[4] = *(const float4*)&As[buf][kk][ty*8 + 4];
            *(float4*)&w[0] = *(const float4*)&Ws[buf][kk][tx*8];
            *(float4*)&w[4] = *(const float4*)&Ws[buf][kk][tx*8 + 4];
#pragma unroll
            for (int i = 0; i < 8; i++)
#pragma unroll
                for (int j = 0; j < 8; j++)
                    acc[i][j] = fmaf(a[i], w[j], acc[i][j]);
        }
        if (pf) {
            int nb = buf ^ 1;
            As[nb][lc+0][lr] = na0.x; As[nb][lc+1][lr] = na0.y; As[nb][lc+2][lr] = na0.z; As[nb][lc+3][lr] = na0.w;
            As[nb][lc+0][lr+64] = na1.x; As[nb][lc+1][lr+64] = na1.y; As[nb][lc+2][lr+64] = na1.z; As[nb][lc+3][lr+64] = na1.w;
            Ws[nb][lc+0][lr] = nw0.x; Ws[nb][lc+1][lr] = nw0.y; Ws[nb][lc+2][lr] = nw0.z; Ws[nb][lc+3][lr] = nw0.w;
            Ws[nb][lc+0][lr+64] = nw1.x; Ws[nb][lc+1][lr+64] = nw1.y; Ws[nb][lc+2][lr+64] = nw1.z; Ws[nb][lc+3][lr+64] = nw1.w;
            __syncthreads();
            buf = nb;
        }
    }

    const int col0 = bn + tx*8;
    if (epi == 2) {
        // GLU: packed cols (even,odd) = (g1,g2); output col = col0/2 + j
        const float s = *sres_p;
        const int oc0 = col0 >> 1;   // multiple of 4
#pragma unroll
        for (int i = 0; i < 8; i++) {
            size_t row = (size_t)(bm + ty*8 + i);
            float* xp = Xout + row*DM + oc0;
            float4 xv = *(float4*)xp;
            xv.x = fmaf(s * acc[i][0], 1.0f/(1.0f + expf(-acc[i][1])), xv.x);
            xv.y = fmaf(s * acc[i][2], 1.0f/(1.0f + expf(-acc[i][3])), xv.y);
            xv.z = fmaf(s * acc[i][4], 1.0f/(1.0f + expf(-acc[i][5])), xv.z);
            xv.w = fmaf(s * acc[i][6], 1.0f/(1.0f + expf(-acc[i][7])), xv.w);
            *(float4*)xp = xv;
        }
    } else if (col0 < N) {
#pragma unroll
        for (int i = 0; i < 8; i++) {
            size_t row = (size_t)(bm + ty*8 + i);
            float4 v0 = make_float4(acc[i][0], acc[i][1], acc[i][2], acc[i][3]);
            float4 v1 = make_float4(acc[i][4], acc[i][5], acc[i][6], acc[i][7]);
            if (epi == 1) {
                float4 x0 = *(const float4*)&Xres[row*N + col0];
                float4 x1 = *(const float4*)&Xres[row*N + col0 + 4];
                float4 d0 = *(const float4*)&Dvec[col0];
                float4 d1 = *(const float4*)&Dvec[col0 + 4];
                v0.x = fmaf(d0.x, x0.x, v0.x); v0.y = fmaf(d0.y, x0.y, v0.y);
                v0.z = fmaf(d0.z, x0.z, v0.z); v0.w = fmaf(d0.w, x0.w, v0.w);
                v1.x = fmaf(d1.x, x1.x, v1.x); v1.y = fmaf(d1.y, x1.y, v1.y);
                v1.z = fmaf(d1.z, x1.z, v1.z); v1.w = fmaf(d1.w, x1.w, v1.w);
            }
            *(float4*)&C[row*N + col0]     = v0;
            *(float4*)&C[row*N + col0 + 4] = v1;
        }
    }
}

// ---------------- chunked LRU scan ----------------
__global__ void scan_local_kernel(const float* __restrict__ Bu, float* __restrict__ H,
                                  const float* __restrict__ lre_g,
                                  const float* __restrict__ lim_g) {
    int n = threadIdx.x;
    int b = blockIdx.x;
    int c = blockIdx.y;
    float lre = lre_g[n], lim = lim_g[n];
    size_t base = ((size_t)b * LSEQ + (size_t)c * CHLEN) * DM + n;
    float hre = 0.0f, him = 0.0f;
#pragma unroll 4
    for (int t = 0; t < CHLEN; ++t) {
        size_t off = base + (size_t)t * DM;
        float bre = Bu[off];
        float bim = Bu[off + DS];
        float nre = fmaf(lre, hre, fmaf(-lim, him, bre));
        float nim = fmaf(lim, hre, fmaf( lre, him, bim));
        hre = nre; him = nim;
        H[off]      = hre;
        H[off + DS] = him;
    }
    int ci = b * NCH + c;
    g_cend[(size_t)ci*2*DS + n]      = hre;
    g_cend[(size_t)ci*2*DS + DS + n] = him;
}

__global__ void scan_carry_kernel(const float* __restrict__ lre_g,
                                  const float* __restrict__ lim_g) {
    int n = threadIdx.x;
    int b = blockIdx.x;
    float lre = lre_g[n], lim = lim_g[n];
    // lamP = lam^CHLEN by 7 squarings (CHLEN = 128)
    float pre = lre, pim = lim;
#pragma unroll
    for (int i = 0; i < 7; i++) {
        float t = pre*pre - pim*pim;
        pim = 2.0f*pre*pim;
        pre = t;
    }
    float sre = 0.0f, sim = 0.0f;
    for (int c = 0; c < NCH; ++c) {
        size_t ci = (size_t)(b * NCH + c) * 2 * DS;
        g_cin[ci + n]      = sre;
        g_cin[ci + DS + n] = sim;
        float ere = g_cend[ci + n];
        float eim = g_cend[ci + DS + n];
        float nre = fmaf(pre, sre, fmaf(-pim, sim, ere));
        float nim = fmaf(pim, sre, fmaf( pre, sim, eim));
        sre = nre; sim = nim;
    }
}

__global__ void scan_fix_kernel(float* __restrict__ H,
                                const float* __restrict__ lre_g,
                                const float* __restrict__ lim_g) {
    int n = threadIdx.x;
    int b = blockIdx.x;
    int c = blockIdx.y + 1;     // chunk 0 needs no fix
    float lre = lre_g[n], lim = lim_g[n];
    size_t ci = (size_t)(b * NCH + c) * 2 * DS;
    float cre = g_cin[ci + n];
    float cim = g_cin[ci + DS + n];
    float pre = lre, pim = lim;   // lam^(t+1), t local
    size_t base = ((size_t)b * LSEQ + (size_t)c * CHLEN) * DM + n;
#pragma unroll 4
    for (int t = 0; t < CHLEN; ++t) {
        size_t off = base + (size_t)t * DM;
        float hre = H[off]      + (pre*cre - pim*cim);
        float him = H[off + DS] + (pre*cim + pim*cre);
        H[off]      = hre;
        H[off + DS] = him;
        float npre = pre*lre - pim*lim;
        float npim = pre*lim + pim*lre;
        pre = npre; pim = npim;
    }
}

// ---------------- host launch ----------------
extern "C" void kernel_launch(void* const* d_in, const int* in_sizes, int n_in,
                              void* d_out, int out_size) {
    const float* u      = (const float*)d_in[0];
    const float* enc_w  = (const float*)d_in[1];
    const float* dec_w  = (const float*)d_in[2];
    const float* nu_log = (const float*)d_in[3];
    const float* th_log = (const float*)d_in[4];
    const float* Bre    = (const float*)d_in[5];
    const float* Bim    = (const float*)d_in[6];
    const float* Cre    = (const float*)d_in[7];
    const float* Cim    = (const float*)d_in[8];
    const float* Dv     = (const float*)d_in[9];
    const float* W1     = (const float*)d_in[10];
    const float* W2     = (const float*)d_in[11];
    const float* rlog   = (const float*)d_in[12];
    float* out = (float*)d_out;

    float *px, *pbu, *ph, *pz, *pWb, *pWc, *pWglu, *plre, *plim, *psres;
    cudaGetSymbolAddress((void**)&px,    g_x);
    cudaGetSymbolAddress((void**)&pbu,   g_bu);
    cudaGetSymbolAddress((void**)&ph,    g_h);
    cudaGetSymbolAddress((void**)&pz,    g_z);
    cudaGetSymbolAddress((void**)&pWb,   g_Wb);
    cudaGetSymbolAddress((void**)&pWc,   g_Wc);
    cudaGetSymbolAddress((void**)&pWglu, g_Wglu);
    cudaGetSymbolAddress((void**)&plre,  g_lre);
    cudaGetSymbolAddress((void**)&plim,  g_lim);
    cudaGetSymbolAddress((void**)&psres, g_sres);

    prep_lam_kernel <<<(NL*DS + 255)/256, 256>>>(nu_log, th_log, rlog);
    prep_wb_kernel  <<<(NL*DM*DM + 255)/256, 256>>>(Bre, Bim);
    prep_wc_kernel  <<<(NL*DM*DM + 255)/256, 256>>>(Cre, Cim);
    prep_wglu_kernel<<<(NL*2*DM*DM + 255)/256, 256>>>(W1, W2);

    // encoder: x = u @ enc_w^T
    sgemm_kernel<<<dim3(DM/BNT, MTOK/BMT), 256>>>(
        u, enc_w, px, MTOK, DM, DIN, 0, nullptr, nullptr, nullptr, nullptr);

    for (int l = 0; l < NL; ++l) {
        const float* lre = plre + l*DS;
        const float* lim = plim + l*DS;
        // Bu packed (gamma folded)
        sgemm_kernel<<<dim3(DM/BNT, MTOK/BMT), 256>>>(
            px, pWb + (size_t)l*DM*DM, pbu, MTOK, DM, DM, 0, nullptr, nullptr, nullptr, nullptr);
        // chunked scan
        scan_local_kernel<<<dim3(NB, NCH), DS>>>(pbu, ph, lre, lim);
        scan_carry_kernel<<<NB, DS>>>(lre, lim);
        scan_fix_kernel<<<dim3(NB, NCH-1), DS>>>(ph, lre, lim);
        // z = Re(C h) + D*x
        sgemm_kernel<<<dim3(DM/BNT, MTOK/BMT), 256>>>(
            ph, pWc + (size_t)l*DM*DM, pz, MTOK, DM, DM, 1, Dv + l*DM, px, nullptr, nullptr);
        // GLU GEMM with fused gate + gated residual into x
        sgemm_kernel<<<dim3(2*DM/BNT, MTOK/BMT), 256>>>(
            pz, pWglu + (size_t)l*2*DM*DM, nullptr, MTOK, 2*DM, DM, 2, nullptr, nullptr, psres + l, px);
    }

    // decoder
    sgemm_kernel<<<dim3((DOUT + BNT-1)/BNT, MTOK/BMT), 256>>>(
        px, dec_w, out, MTOK, DOUT, DM, 0, nullptr, nullptr, nullptr, nullptr);
}

// round 4
// speedup vs baseline: 2.0227x; 1.7579x over previous
#include <cuda_runtime.h>
#include <cuda_bf16.h>
#include <math.h>
#include <string.h>
#include <stdint.h>

#define NB    8
#define LSEQ  2048
#define MTOK  (NB*LSEQ)     // 16384 tokens
#define DIN   64
#define DOUT  64
#define DM    512
#define DS    256
#define NL    4
#define NCH   16
#define CHLEN (LSEQ/NCH)    // 128

// ---------------- scratch (device globals; no allocation allowed) ----------------
__device__ float g_x   [MTOK*DM];
__device__ float g_bu  [MTOK*DM];          // Bu packed [re(256) | im(256)]
__device__ float g_h   [MTOK*DM];          // h  packed [re | im]
__device__ float g_z   [MTOK*DM];          // LRU output
__device__ float g_Wb  [NL*DM*DM];         // gamma-scaled [Bre ; Bim] rows
__device__ float g_Wc  [NL*DM*DM];         // [Cre | -Cim] along K
__device__ float g_Wglu[NL*2*DM*DM];       // interleaved rows: 2o=W1[o], 2o+1=W2[o]
__device__ float g_lre [NL*DS];
__device__ float g_lim [NL*DS];
__device__ float g_gam [NL*DS];
__device__ float g_sres[NL];
__device__ float g_cend[NB*NCH*2*DS];
__device__ float g_cin [NB*NCH*2*DS];

// ---------------- helpers ----------------
__device__ __forceinline__ uint32_t smem_u32(const void* p) {
    uint32_t a;
    asm("{ .reg .u64 t; cvta.to.shared.u64 t, %1; cvt.u32.u64 %0, t; }" : "=r"(a) : "l"(p));
    return a;
}
__device__ __forceinline__ uint32_t sw128(uint32_t b) { return b ^ ((b >> 3) & 0x70); }

__device__ __forceinline__ void ldsm4(uint32_t* r, uint32_t addr) {
    asm volatile("ldmatrix.sync.aligned.m8n8.x4.shared.b16 {%0,%1,%2,%3}, [%4];"
                 : "=r"(r[0]), "=r"(r[1]), "=r"(r[2]), "=r"(r[3]) : "r"(addr));
}
__device__ __forceinline__ void mma_bf16(float* c, const uint32_t* a, const uint32_t* b) {
    asm volatile(
        "mma.sync.aligned.m16n8k16.row.col.f32.bf16.bf16.f32 "
        "{%0,%1,%2,%3}, {%4,%5,%6,%7}, {%8,%9}, {%0,%1,%2,%3};"
        : "+f"(c[0]), "+f"(c[1]), "+f"(c[2]), "+f"(c[3])
        : "r"(a[0]), "r"(a[1]), "r"(a[2]), "r"(a[3]), "r"(b[0]), "r"(b[1]));
}

struct Pack8 { uint4 hi, lo; };

__device__ __forceinline__ uint32_t pk(float a, float b) {
    __nv_bfloat162 t = __floats2bfloat162_rn(a, b);
    uint32_t u; memcpy(&u, &t, 4); return u;
}

// load 8 fp32, split into bf16 hi (16B) + lo (16B)
__device__ __forceinline__ Pack8 load_split(const float* p, bool valid) {
    Pack8 o;
    float4 v0 = make_float4(0.f,0.f,0.f,0.f), v1 = v0;
    if (valid) {
        v0 = *reinterpret_cast<const float4*>(p);
        v1 = *reinterpret_cast<const float4*>(p + 4);
    }
    o.hi.x = pk(v0.x, v0.y); o.hi.y = pk(v0.z, v0.w);
    o.hi.z = pk(v1.x, v1.y); o.hi.w = pk(v1.z, v1.w);
    __nv_bfloat162 h;
    float r[8];
    memcpy(&h, &o.hi.x, 4); r[0] = v0.x - __bfloat162float(h.x); r[1] = v0.y - __bfloat162float(h.y);
    memcpy(&h, &o.hi.y, 4); r[2] = v0.z - __bfloat162float(h.x); r[3] = v0.w - __bfloat162float(h.y);
    memcpy(&h, &o.hi.z, 4); r[4] = v1.x - __bfloat162float(h.x); r[5] = v1.y - __bfloat162float(h.y);
    memcpy(&h, &o.hi.w, 4); r[6] = v1.z - __bfloat162float(h.x); r[7] = v1.w - __bfloat162float(h.y);
    o.lo.x = pk(r[0], r[1]); o.lo.y = pk(r[2], r[3]);
    o.lo.z = pk(r[4], r[5]); o.lo.w = pk(r[6], r[7]);
    return o;
}

__device__ __forceinline__ void store_pair(char* base, int row, int q, const Pack8& p8) {
    *reinterpret_cast<uint4*>(base + sw128((uint32_t)(row*128 + q*16)))      = p8.hi;
    *reinterpret_cast<uint4*>(base + sw128((uint32_t)(row*128 + 64 + q*16))) = p8.lo;
}

// ---------------- prep kernels ----------------
__global__ void prep_lam_kernel(const float* __restrict__ nu_log,
                                const float* __restrict__ th_log,
                                const float* __restrict__ rlog) {
    int i = blockIdx.x * blockDim.x + threadIdx.x;
    if (i < NL*DS) {
        float nu = expf(nu_log[i]);
        float r  = expf(-nu);
        float th = expf(th_log[i]);
        g_lre[i] = r * cosf(th);
        g_lim[i] = r * sinf(th);
        g_gam[i] = sqrtf(fmaxf(1.0f - r*r, 0.0f));
    }
    if (i < NL) g_sres[i] = 1.0f / (1.0f + expf(-rlog[i]));
}

__global__ void prep_wb_kernel(const float* __restrict__ Bre,
                               const float* __restrict__ Bim) {
    int idx = blockIdx.x * blockDim.x + threadIdx.x;
    if (idx >= NL*DM*DM) return;
    int l   = idx / (DM*DM);
    int rem = idx - l*(DM*DM);
    int n   = rem / DM;
    int k   = rem - n*DM;
    float v;
    if (n < DS) v = g_gam[l*DS + n]      * Bre[((size_t)l*DS + n)*DM + k];
    else        v = g_gam[l*DS + n - DS] * Bim[((size_t)l*DS + (n-DS))*DM + k];
    g_Wb[idx] = v;
}

__global__ void prep_wc_kernel(const float* __restrict__ Cre,
                               const float* __restrict__ Cim) {
    int idx = blockIdx.x * blockDim.x + threadIdx.x;
    if (idx >= NL*DM*DM) return;
    int l   = idx / (DM*DM);
    int rem = idx - l*(DM*DM);
    int d   = rem / DM;
    int k   = rem - d*DM;
    float v;
    if (k < DS) v =  Cre[((size_t)l*DM + d)*DS + k];
    else        v = -Cim[((size_t)l*DM + d)*DS + (k-DS)];
    g_Wc[idx] = v;
}

__global__ void prep_wglu_kernel(const float* __restrict__ W1,
                                 const float* __restrict__ W2) {
    int idx = blockIdx.x * blockDim.x + threadIdx.x;
    if (idx >= NL*2*DM*DM) return;
    int l   = idx / (2*DM*DM);
    int rem = idx - l*(2*DM*DM);
    int n   = rem / DM;
    int k   = rem - n*DM;
    int o   = n >> 1;
    float v = (n & 1) ? W2[((size_t)l*DM + o)*DM + k]
                      : W1[((size_t)l*DM + o)*DM + k];
    g_Wglu[idx] = v;
}

// ---------------- HMMA GEMM (mma.sync bf16 3-way split) ----------------
// C[m,n] = sum_k A[m,k]*W[n,k]. CTA 128x128, BK=32, 8 warps (warp tile 64x32).
// EPI: 0 plain, 1 += Dvec[n]*Xres[m,n], 2 GLU: Xout[m,n/2] += s*even*sigmoid(odd)
#define STAGEB 32768   // A tile 16KB (hi|lo interleaved rows) + W tile 16KB

template<int EPI, bool WGUARD>
__global__ __launch_bounds__(256, 1)
void hmma_gemm(const float* __restrict__ A, const float* __restrict__ W,
               float* __restrict__ C, int K, int Ntot,
               const float* __restrict__ Dvec, const float* __restrict__ Xres,
               const float* __restrict__ sres_p, float* __restrict__ Xout) {
    extern __shared__ char smem[];
    const int tid  = threadIdx.x;
    const int wid  = tid >> 5;
    const int lane = tid & 31;
    const int wm   = wid & 1;      // 0-1 along M (64 rows each)
    const int wn   = wid >> 1;     // 0-3 along N (32 cols each)
    const int bm   = blockIdx.y * 128;
    const int bn   = blockIdx.x * 128;

    float acc[4][4][4];
#pragma unroll
    for (int i = 0; i < 4; i++)
#pragma unroll
        for (int j = 0; j < 4; j++)
#pragma unroll
            for (int q = 0; q < 4; q++) acc[i][j][q] = 0.0f;

    const int NK = K >> 5;   // chunks of 32
    const int frow = tid >> 2;       // fill row (0..63), +64 second iter
    const int fq   = tid & 3;        // fill quarter

    // prologue: chunk 0 -> buf 0
    Pack8 pa0, pa1, pw0, pw1;
    pa0 = load_split(A + (size_t)(bm + frow     )*K + fq*8, true);
    pa1 = load_split(A + (size_t)(bm + frow + 64)*K + fq*8, true);
    pw0 = load_split(W + (size_t)(bn + frow     )*K + fq*8, !WGUARD || (bn + frow      < Ntot));
    pw1 = load_split(W + (size_t)(bn + frow + 64)*K + fq*8, !WGUARD || (bn + frow + 64 < Ntot));
    {
        char* As = smem;
        char* Ws = smem + 16384;
        store_pair(As, frow,      fq, pa0);
        store_pair(As, frow + 64, fq, pa1);
        store_pair(Ws, frow,      fq, pw0);
        store_pair(Ws, frow + 64, fq, pw1);
    }
    __syncthreads();

    // per-lane ldmatrix address components
    const int a_row = wm*64 + (lane & 7) + ((lane >> 3) & 1)*8;   // + 16*i
    const int a_kb  = ((lane >> 4) << 4);                          // 0 or 16
    const int b_sub = lane >> 3;
    const int b_row = wn*32 + (lane & 7) + (b_sub >> 1)*8;         // + 16*jj
    const int b_kb  = (b_sub & 1) << 4;

    for (int t = 0; t < NK; ++t) {
        const int buf = t & 1;
        if (t + 1 < NK) {
            const int k0 = (t + 1) << 5;
            pa0 = load_split(A + (size_t)(bm + frow     )*K + k0 + fq*8, true);
            pa1 = load_split(A + (size_t)(bm + frow + 64)*K + k0 + fq*8, true);
            pw0 = load_split(W + (size_t)(bn + frow     )*K + k0 + fq*8, !WGUARD || (bn + frow      < Ntot));
            pw1 = load_split(W + (size_t)(bn + frow + 64)*K + k0 + fq*8, !WGUARD || (bn + frow + 64 < Ntot));
        }
        const uint32_t As = smem_u32(smem + buf*STAGEB);
        const uint32_t Ws = As + 16384;
#pragma unroll
        for (int s = 0; s < 2; ++s) {
            uint32_t ahi[4][4], alo[4][4], bhi[4][2], blo[4][2];
#pragma unroll
            for (int i = 0; i < 4; i++) {
                uint32_t base = (uint32_t)((a_row + 16*i)*128 + s*32 + a_kb);
                ldsm4(ahi[i], As + sw128(base));
                ldsm4(alo[i], As + sw128(base + 64));
            }
#pragma unroll
            for (int jj = 0; jj < 2; jj++) {
                uint32_t base = (uint32_t)((b_row + 16*jj)*128 + s*32 + b_kb);
                uint32_t r[4];
                ldsm4(r, Ws + sw128(base));
                bhi[2*jj][0] = r[0]; bhi[2*jj][1] = r[1];
                bhi[2*jj+1][0] = r[2]; bhi[2*jj+1][1] = r[3];
                ldsm4(r, Ws + sw128(base + 64));
                blo[2*jj][0] = r[0]; blo[2*jj][1] = r[1];
                blo[2*jj+1][0] = r[2]; blo[2*jj+1][1] = r[3];
            }
#pragma unroll
            for (int i = 0; i < 4; i++)
#pragma unroll
                for (int j = 0; j < 4; j++) {
                    mma_bf16(acc[i][j], ahi[i], bhi[j]);
                    mma_bf16(acc[i][j], ahi[i], blo[j]);
                    mma_bf16(acc[i][j], alo[i], bhi[j]);
                }
        }
        if (t + 1 < NK) {
            char* As2 = smem + (buf ^ 1)*STAGEB;
            char* Ws2 = As2 + 16384;
            __syncthreads();   // everyone done reading buf^1 from 2 chunks ago
            store_pair(As2, frow,      fq, pa0);
            store_pair(As2, frow + 64, fq, pa1);
            store_pair(Ws2, frow,      fq, pw0);
            store_pair(Ws2, frow + 64, fq, pw1);
            __syncthreads();
        }
    }

    // epilogue
    const int gid = lane >> 2;      // 0..7
    const int tg  = lane & 3;       // 0..3
#pragma unroll
    for (int i = 0; i < 4; i++) {
        const int r0 = bm + wm*64 + i*16 + gid;
#pragma unroll
        for (int j = 0; j < 4; j++) {
            const int col = bn + wn*32 + j*8 + tg*2;
            if (EPI == 2) {
                const float s = *sres_p;
                const int oc = col >> 1;
                float* xp0 = Xout + (size_t)r0 * DM + oc;
                float* xp1 = Xout + (size_t)(r0+8) * DM + oc;
                *xp0 = fmaf(s * acc[i][j][0], 1.0f/(1.0f + expf(-acc[i][j][1])), *xp0);
                *xp1 = fmaf(s * acc[i][j][2], 1.0f/(1.0f + expf(-acc[i][j][3])), *xp1);
            } else {
                if (WGUARD && col >= Ntot) continue;
                float2 v0 = make_float2(acc[i][j][0], acc[i][j][1]);
                float2 v1 = make_float2(acc[i][j][2], acc[i][j][3]);
                if (EPI == 1) {
                    const float2 d  = *reinterpret_cast<const float2*>(Dvec + col);
                    const float2 x0 = *reinterpret_cast<const float2*>(Xres + (size_t)r0*Ntot + col);
                    const float2 x1 = *reinterpret_cast<const float2*>(Xres + (size_t)(r0+8)*Ntot + col);
                    v0.x = fmaf(d.x, x0.x, v0.x); v0.y = fmaf(d.y, x0.y, v0.y);
                    v1.x = fmaf(d.x, x1.x, v1.x); v1.y = fmaf(d.y, x1.y, v1.y);
                }
                *reinterpret_cast<float2*>(C + (size_t)r0*Ntot + col)     = v0;
                *reinterpret_cast<float2*>(C + (size_t)(r0+8)*Ntot + col) = v1;
            }
        }
    }
}

// ---------------- chunked LRU scan ----------------
__global__ void scan_local_kernel(const float* __restrict__ Bu, float* __restrict__ H,
                                  const float* __restrict__ lre_g,
                                  const float* __restrict__ lim_g) {
    int n = threadIdx.x;
    int b = blockIdx.x;
    int c = blockIdx.y;
    float lre = lre_g[n], lim = lim_g[n];
    size_t base = ((size_t)b * LSEQ + (size_t)c * CHLEN) * DM + n;
    float hre = 0.0f, him = 0.0f;
#pragma unroll 4
    for (int t = 0; t < CHLEN; ++t) {
        size_t off = base + (size_t)t * DM;
        float bre = Bu[off];
        float bim = Bu[off + DS];
        float nre = fmaf(lre, hre, fmaf(-lim, him, bre));
        float nim = fmaf(lim, hre, fmaf( lre, him, bim));
        hre = nre; him = nim;
        H[off]      = hre;
        H[off + DS] = him;
    }
    int ci = b * NCH + c;
    g_cend[(size_t)ci*2*DS + n]      = hre;
    g_cend[(size_t)ci*2*DS + DS + n] = him;
}

__global__ void scan_carry_kernel(const float* __restrict__ lre_g,
                                  const float* __restrict__ lim_g) {
    int n = threadIdx.x;
    int b = blockIdx.x;
    float lre = lre_g[n], lim = lim_g[n];
    float pre = lre, pim = lim;
#pragma unroll
    for (int i = 0; i < 7; i++) {     // lam^128
        float t = pre*pre - pim*pim;
        pim = 2.0f*pre*pim;
        pre = t;
    }
    float sre = 0.0f, sim = 0.0f;
    for (int c = 0; c < NCH; ++c) {
        size_t ci = (size_t)(b * NCH + c) * 2 * DS;
        g_cin[ci + n]      = sre;
        g_cin[ci + DS + n] = sim;
        float ere = g_cend[ci + n];
        float eim = g_cend[ci + DS + n];
        float nre = fmaf(pre, sre, fmaf(-pim, sim, ere));
        float nim = fmaf(pim, sre, fmaf( pre, sim, eim));
        sre = nre; sim = nim;
    }
}

__global__ void scan_fix_kernel(float* __restrict__ H,
                                const float* __restrict__ lre_g,
                                const float* __restrict__ lim_g) {
    int n = threadIdx.x;
    int b = blockIdx.x;
    int c = blockIdx.y + 1;
    float lre = lre_g[n], lim = lim_g[n];
    size_t ci = (size_t)(b * NCH + c) * 2 * DS;
    float cre = g_cin[ci + n];
    float cim = g_cin[ci + DS + n];
    float pre = lre, pim = lim;
    size_t base = ((size_t)b * LSEQ + (size_t)c * CHLEN) * DM + n;
#pragma unroll 4
    for (int t = 0; t < CHLEN; ++t) {
        size_t off = base + (size_t)t * DM;
        float hre = H[off]      + (pre*cre - pim*cim);
        float him = H[off + DS] + (pre*cim + pim*cre);
        H[off]      = hre;
        H[off + DS] = him;
        float npre = pre*lre - pim*lim;
        float npim = pre*lim + pim*lre;
        pre = npre; pim = npim;
    }
}

// ---------------- host launch ----------------
extern "C" void kernel_launch(void* const* d_in, const int* in_sizes, int n_in,
                              void* d_out, int out_size) {
    const float* u      = (const float*)d_in[0];
    const float* enc_w  = (const float*)d_in[1];
    const float* dec_w  = (const float*)d_in[2];
    const float* nu_log = (const float*)d_in[3];
    const float* th_log = (const float*)d_in[4];
    const float* Bre    = (const float*)d_in[5];
    const float* Bim    = (const float*)d_in[6];
    const float* Cre    = (const float*)d_in[7];
    const float* Cim    = (const float*)d_in[8];
    const float* Dv     = (const float*)d_in[9];
    const float* W1     = (const float*)d_in[10];
    const float* W2     = (const float*)d_in[11];
    const float* rlog   = (const float*)d_in[12];
    float* out = (float*)d_out;

    float *px, *pbu, *ph, *pz, *pWb, *pWc, *pWglu, *plre, *plim, *psres;
    cudaGetSymbolAddress((void**)&px,    g_x);
    cudaGetSymbolAddress((void**)&pbu,   g_bu);
    cudaGetSymbolAddress((void**)&ph,    g_h);
    cudaGetSymbolAddress((void**)&pz,    g_z);
    cudaGetSymbolAddress((void**)&pWb,   g_Wb);
    cudaGetSymbolAddress((void**)&pWc,   g_Wc);
    cudaGetSymbolAddress((void**)&pWglu, g_Wglu);
    cudaGetSymbolAddress((void**)&plre,  g_lre);
    cudaGetSymbolAddress((void**)&plim,  g_lim);
    cudaGetSymbolAddress((void**)&psres, g_sres);

    const int SMEM = 2 * STAGEB;   // 64 KB
    cudaFuncSetAttribute(hmma_gemm<0,false>, cudaFuncAttributeMaxDynamicSharedMemorySize, SMEM);
    cudaFuncSetAttribute(hmma_gemm<1,false>, cudaFuncAttributeMaxDynamicSharedMemorySize, SMEM);
    cudaFuncSetAttribute(hmma_gemm<2,false>, cudaFuncAttributeMaxDynamicSharedMemorySize, SMEM);
    cudaFuncSetAttribute(hmma_gemm<0,true>,  cudaFuncAttributeMaxDynamicSharedMemorySize, SMEM);

    prep_lam_kernel <<<(NL*DS + 255)/256, 256>>>(nu_log, th_log, rlog);
    prep_wb_kernel  <<<(NL*DM*DM + 255)/256, 256>>>(Bre, Bim);
    prep_wc_kernel  <<<(NL*DM*DM + 255)/256, 256>>>(Cre, Cim);
    prep_wglu_kernel<<<(NL*2*DM*DM + 255)/256, 256>>>(W1, W2);

    // encoder: x = u @ enc_w^T  (K=64)
    hmma_gemm<0,false><<<dim3(DM/128, MTOK/128), 256, SMEM>>>(
        u, enc_w, px, DIN, DM, nullptr, nullptr, nullptr, nullptr);

    for (int l = 0; l < NL; ++l) {
        const float* lre = plre + l*DS;
        const float* lim = plim + l*DS;
        // Bu packed (gamma folded)
        hmma_gemm<0,false><<<dim3(DM/128, MTOK/128), 256, SMEM>>>(
            px, pWb + (size_t)l*DM*DM, pbu, DM, DM, nullptr, nullptr, nullptr, nullptr);
        // chunked scan
        scan_local_kernel<<<dim3(NB, NCH), DS>>>(pbu, ph, lre, lim);
        scan_carry_kernel<<<NB, DS>>>(lre, lim);
        scan_fix_kernel<<<dim3(NB, NCH-1), DS>>>(ph, lre, lim);
        // z = Re(C h) + D*x
        hmma_gemm<1,false><<<dim3(DM/128, MTOK/128), 256, SMEM>>>(
            ph, pWc + (size_t)l*DM*DM, pz, DM, DM, Dv + l*DM, px, nullptr, nullptr);
        // GLU GEMM (N = 1024 interleaved) fused gate + gated residual into x
        hmma_gemm<2,false><<<dim3(2*DM/128, MTOK/128), 256, SMEM>>>(
            pz, pWglu + (size_t)l*2*DM*DM, nullptr, DM, 2*DM, nullptr, nullptr, psres + l, px);
    }

    // decoder: out = x @ dec_w^T  (N = 64, guarded)
    hmma_gemm<0,true><<<dim3(1, MTOK/128), 256, SMEM>>>(
        px, dec_w, out, DM, DOUT, nullptr, nullptr, nullptr, nullptr);
}